// round 11
// baseline (speedup 1.0000x reference)
#include <cuda_runtime.h>
#include <cstdint>

#define BB 512
#define NN 4096
#define RR 4097
#define TPB 512
#define EPT 8

#define CONTENT_PAD 1024
#define CONTENT_EOS 1025

__constant__ int c_posEOS[3] = {129, 257, 1025};
__constant__ int c_posPAD[3] = {128, 256, 1024};

// exact int->float for 0 <= x < 2^23 without I2F
__device__ __forceinline__ float i2f_fast(int x) {
    return __int_as_float(0x4B000000 | x) - 8388608.0f;
}

__global__ __launch_bounds__(TPB) void triple_grain_kernel(
    const int* __restrict__ in0,
    const int* __restrict__ in1,
    float* __restrict__ out)
{
    const int b    = blockIdx.x;
    const int g    = blockIdx.y;          // grain stream handled by this CTA
    const int tid  = threadIdx.x;
    const int lane = tid & 31;
    const int wid  = tid >> 5;

    __shared__ float cbuf[NN + 4];        // staged content (float), shifted by b&3
    __shared__ float pbuf[NN + 4];        // staged position (float)
    __shared__ int warp_sums[16];

    const int* row0 = in0 + (long long)b * NN;
    const int* row1 = in1 + (long long)b * NN;

    // ---- load 8 contiguous elements from each candidate input ----
    int4 a0 = ((const int4*)row0)[tid * 2 + 0];
    int4 a1 = ((const int4*)row0)[tid * 2 + 1];
    int4 c0 = ((const int4*)row1)[tid * 2 + 0];
    int4 c1 = ((const int4*)row1)[tid * 2 + 1];
    int as[EPT] = {a0.x, a0.y, a0.z, a0.w, a1.x, a1.y, a1.z, a1.w};
    int cs[EPT] = {c0.x, c0.y, c0.z, c0.w, c1.x, c1.y, c1.z, c1.w};

    // ---- identify which input is the grain array (values all in {0,1,2}) ----
    int a_ge3 = 0;
#pragma unroll
    for (int i = 0; i < EPT; i++) a_ge3 |= ((unsigned)as[i] >= 3u);
    const int in0_is_indices = __syncthreads_or(a_ge3);

    int flags[EPT], vs[EPT];
    int cnt = 0;
#pragma unroll
    for (int i = 0; i < EPT; i++) {
        int gv = in0_is_indices ? cs[i] : as[i];
        vs[i]  = in0_is_indices ? as[i] : cs[i];
        flags[i] = (gv == g);
        cnt += flags[i];
    }

    // ---- block inclusive scan of per-thread count ----
    int inc = cnt;
#pragma unroll
    for (int d = 1; d < 32; d <<= 1) {
        int v = __shfl_up_sync(0xffffffffu, inc, d);
        if (lane >= d) inc += v;
    }
    if (lane == 31) warp_sums[wid] = inc;
    __syncthreads();
    if (wid == 0) {
        int v = (lane < 16) ? warp_sums[lane] : 0;
#pragma unroll
        for (int d = 1; d < 16; d <<= 1) {
            int u = __shfl_up_sync(0xffffffffu, v, d);
            if (lane >= d) v += u;
        }
        if (lane < 16) warp_sums[lane] = v;
    }
    __syncthreads();

    int off = inc - cnt + (wid > 0 ? warp_sums[wid - 1] : 0);
    const int cg = warp_sums[15];         // total selected in this stream

    // staging shift so that smem index (shift + j) is 16B-aligned when
    // j ≡ pre (mod 4):  pre = (4-(b&3))&3, shift = b&3  →  shift+pre ≡ 0 mod 4
    const int shift = b & 3;

    // ---- stable scatter of floats into smem ----
    const int base_pos = tid * EPT;
#pragma unroll
    for (int i = 0; i < EPT; i++) {
        if (flags[i]) {
            cbuf[shift + off] = i2f_fast(vs[i]);
            pbuf[shift + off] = i2f_fast(base_pos + i);
            off++;
        }
    }
    __syncthreads();

    // ---- vectorized float32 output of this CTA's 3 rows ----
    const int pe = c_posEOS[g], pp = c_posPAD[g];
    const float fg = (float)g;

    float* oc = out + ((long long)g       * BB + b) * RR;   // content
    float* op = out + ((long long)(3 + g) * BB + b) * RR;   // position
    float* os = out + ((long long)(6 + g) * BB + b) * RR;   // segment

    const int pre   = (4 - (b & 3)) & 3;
    const int nvec  = (RR - pre) >> 2;
    const int tailn = (RR - pre) & 3;

    const float4 s4    = make_float4(fg, fg, fg, fg);
    const float4 cpad4 = make_float4(CONTENT_PAD, CONTENT_PAD, CONTENT_PAD, CONTENT_PAD);
    const float4 ppad4 = make_float4((float)pp, (float)pp, (float)pp, (float)pp);

    // scalar prologue + tail (<= 6 elements)
    const int nscal = pre + tailn;
    if (tid < nscal) {
        int j = (tid < pre) ? tid : (pre + 4 * nvec + (tid - pre));
        float cv, pv;
        if (j < cg)       { cv = cbuf[shift + j]; pv = pbuf[shift + j]; }
        else if (j == cg) { cv = (float)CONTENT_EOS; pv = (float)pe; }
        else              { cv = (float)CONTENT_PAD; pv = (float)pp; }
        __stcs(oc + j, cv);
        __stcs(op + j, pv);
        __stcs(os + j, fg);
    }

    // vector interior: ~1024 chunks / 512 threads = 2 per thread
    for (int v = tid; v < nvec; v += TPB) {
        const int j0 = pre + 4 * v;
        float4 c4, p4;
        if (j0 + 3 < cg) {
            c4 = *(const float4*)(cbuf + shift + j0);   // aligned LDS.128
            p4 = *(const float4*)(pbuf + shift + j0);
        } else if (j0 > cg) {
            c4 = cpad4;
            p4 = ppad4;
        } else {
            float cc[4], ppv[4];
#pragma unroll
            for (int k = 0; k < 4; k++) {
                int j = j0 + k;
                if (j < cg)       { cc[k] = cbuf[shift + j]; ppv[k] = pbuf[shift + j]; }
                else if (j == cg) { cc[k] = (float)CONTENT_EOS; ppv[k] = (float)pe; }
                else              { cc[k] = (float)CONTENT_PAD; ppv[k] = (float)pp; }
            }
            c4 = make_float4(cc[0], cc[1], cc[2], cc[3]);
            p4 = make_float4(ppv[0], ppv[1], ppv[2], ppv[3]);
        }
        __stcs((float4*)(oc + j0), c4);
        __stcs((float4*)(op + j0), p4);
        __stcs((float4*)(os + j0), s4);
    }
}

extern "C" void kernel_launch(void* const* d_in, const int* in_sizes, int n_in,
                              void* d_out, int out_size)
{
    const int* in0 = (const int*)d_in[0];
    const int* in1 = (const int*)d_in[1];
    float* out = (float*)d_out;
    dim3 grid(BB, 3);
    triple_grain_kernel<<<grid, TPB>>>(in0, in1, out);
}

// round 12
// speedup vs baseline: 1.0861x; 1.0861x over previous
#include <cuda_runtime.h>
#include <cstdint>

#define BB 512
#define NN 4096
#define RR 4097
#define TPB 512
#define EPT 8

#define CONTENT_PAD 1024
#define CONTENT_EOS 1025

// packed word: val in bits [0,11), pos in bits [11,23)
#define PACK(v, p)   ((v) | ((p) << 11))

__constant__ int c_posEOS[3] = {129, 257, 1025};
__constant__ int c_posPAD[3] = {128, 256, 1024};

// exact int->float for 0 <= x < 2^23 without I2F (LOP3 + FADD)
__device__ __forceinline__ float i2f_fast(int x) {
    return __int_as_float(0x4B000000 | x) - 8388608.0f;
}
__device__ __forceinline__ float unpack_v(int w) { return i2f_fast(w & 0x7FF); }
__device__ __forceinline__ float unpack_p(int w) { return i2f_fast(w >> 11); }

__global__ __launch_bounds__(TPB) void triple_grain_kernel(
    const int* __restrict__ in0,
    const int* __restrict__ in1,
    float* __restrict__ out)
{
    const int b    = blockIdx.x;
    const int g    = blockIdx.y;          // grain stream handled by this CTA
    const int tid  = threadIdx.x;
    const int lane = tid & 31;
    const int wid  = tid >> 5;

    __shared__ int buf[NN + 4];           // packed staging, shifted by b&3
    __shared__ int warp_sums[16];

    const int* row0 = in0 + (long long)b * NN;
    const int* row1 = in1 + (long long)b * NN;

    // ---- load 8 contiguous elements from each candidate input ----
    int4 a0 = ((const int4*)row0)[tid * 2 + 0];
    int4 a1 = ((const int4*)row0)[tid * 2 + 1];
    int4 c0 = ((const int4*)row1)[tid * 2 + 0];
    int4 c1 = ((const int4*)row1)[tid * 2 + 1];
    int as[EPT] = {a0.x, a0.y, a0.z, a0.w, a1.x, a1.y, a1.z, a1.w};
    int cs[EPT] = {c0.x, c0.y, c0.z, c0.w, c1.x, c1.y, c1.z, c1.w};

    // ---- identify which input is the grain array (values all in {0,1,2}) ----
    int a_ge3 = 0;
#pragma unroll
    for (int i = 0; i < EPT; i++) a_ge3 |= ((unsigned)as[i] >= 3u);
    const int in0_is_indices = __syncthreads_or(a_ge3);

    int flags[EPT], vs[EPT];
    int cnt = 0;
#pragma unroll
    for (int i = 0; i < EPT; i++) {
        int gv = in0_is_indices ? cs[i] : as[i];
        vs[i]  = in0_is_indices ? as[i] : cs[i];
        flags[i] = (gv == g);
        cnt += flags[i];
    }

    // ---- block inclusive scan of per-thread count ----
    int inc = cnt;
#pragma unroll
    for (int d = 1; d < 32; d <<= 1) {
        int v = __shfl_up_sync(0xffffffffu, inc, d);
        if (lane >= d) inc += v;
    }
    if (lane == 31) warp_sums[wid] = inc;
    __syncthreads();
    if (wid == 0) {
        int v = (lane < 16) ? warp_sums[lane] : 0;
#pragma unroll
        for (int d = 1; d < 16; d <<= 1) {
            int u = __shfl_up_sync(0xffffffffu, v, d);
            if (lane >= d) v += u;
        }
        if (lane < 16) warp_sums[lane] = v;
    }
    __syncthreads();

    int off = inc - cnt + (wid > 0 ? warp_sums[wid - 1] : 0);
    const int cg = warp_sums[15];         // total selected in this stream

    // staging shift so that smem index (shift + j) is 16B-aligned at chunk
    // starts: pre = (4-(b&3))&3, shift = b&3 → shift+pre ≡ 0 (mod 4)
    const int shift = b & 3;

    // ---- stable scatter of packed (val|pos) into smem (1 STS.32/elem) ----
    const int base_pos = tid * EPT;
#pragma unroll
    for (int i = 0; i < EPT; i++) {
        if (flags[i]) {
            buf[shift + off] = PACK(vs[i], base_pos + i);
            off++;
        }
    }
    __syncthreads();

    // ---- vectorized float32 output of this CTA's 3 rows ----
    const int pe = c_posEOS[g], pp = c_posPAD[g];
    const float fg = (float)g;

    float* oc = out + ((long long)g       * BB + b) * RR;   // content
    float* op = out + ((long long)(3 + g) * BB + b) * RR;   // position
    float* os = out + ((long long)(6 + g) * BB + b) * RR;   // segment

    const int pre   = (4 - (b & 3)) & 3;
    const int nvec  = (RR - pre) >> 2;
    const int tailn = (RR - pre) & 3;

    const float4 s4    = make_float4(fg, fg, fg, fg);
    const float4 cpad4 = make_float4(CONTENT_PAD, CONTENT_PAD, CONTENT_PAD, CONTENT_PAD);
    const float4 ppad4 = make_float4((float)pp, (float)pp, (float)pp, (float)pp);

    // scalar prologue + tail (<= 6 elements)
    const int nscal = pre + tailn;
    if (tid < nscal) {
        int j = (tid < pre) ? tid : (pre + 4 * nvec + (tid - pre));
        float cv, pv;
        if (j < cg)       { int w = buf[shift + j]; cv = unpack_v(w); pv = unpack_p(w); }
        else if (j == cg) { cv = (float)CONTENT_EOS; pv = (float)pe; }
        else              { cv = (float)CONTENT_PAD; pv = (float)pp; }
        __stcs(oc + j, cv);
        __stcs(op + j, pv);
        __stcs(os + j, fg);
    }

    // vector interior: ~1024 chunks / 512 threads = 2 per thread
    for (int v = tid; v < nvec; v += TPB) {
        const int j0 = pre + 4 * v;
        float4 c4, p4;
        if (j0 + 3 < cg) {
            int4 w = *(const int4*)(buf + shift + j0);      // aligned LDS.128
            c4 = make_float4(unpack_v(w.x), unpack_v(w.y),
                             unpack_v(w.z), unpack_v(w.w));
            p4 = make_float4(unpack_p(w.x), unpack_p(w.y),
                             unpack_p(w.z), unpack_p(w.w));
        } else if (j0 > cg) {
            c4 = cpad4;
            p4 = ppad4;
        } else {
            float cc[4], ppv[4];
#pragma unroll
            for (int k = 0; k < 4; k++) {
                int j = j0 + k;
                if (j < cg)       { int w = buf[shift + j]; cc[k] = unpack_v(w); ppv[k] = unpack_p(w); }
                else if (j == cg) { cc[k] = (float)CONTENT_EOS; ppv[k] = (float)pe; }
                else              { cc[k] = (float)CONTENT_PAD; ppv[k] = (float)pp; }
            }
            c4 = make_float4(cc[0], cc[1], cc[2], cc[3]);
            p4 = make_float4(ppv[0], ppv[1], ppv[2], ppv[3]);
        }
        __stcs((float4*)(oc + j0), c4);
        __stcs((float4*)(op + j0), p4);
        __stcs((float4*)(os + j0), s4);
    }
}

extern "C" void kernel_launch(void* const* d_in, const int* in_sizes, int n_in,
                              void* d_out, int out_size)
{
    const int* in0 = (const int*)d_in[0];
    const int* in1 = (const int*)d_in[1];
    float* out = (float*)d_out;
    dim3 grid(BB, 3);
    triple_grain_kernel<<<grid, TPB>>>(in0, in1, out);
}